// round 1
// baseline (speedup 1.0000x reference)
#include <cuda_runtime.h>

#define EMBED 1024
#define SEQ   2048
#define BATCH 4
#define HEADS 16
#define HDIM  64

// Scratch (static device globals: allocation-free per harness rules)
__device__ float g_qkv[(size_t)BATCH * SEQ * 3 * EMBED];   // ~100.7 MB
__device__ float g_attn[(size_t)BATCH * SEQ * EMBED];      // ~33.5 MB

// ---------------------------------------------------------------------------
// Tiled SGEMM with bias: C[M,N] = A[M,K] @ B[K,N] + bias[N]
// BM=BN=128, BK=8, 256 threads, 8x8 register tile per thread.
// Assumes M%128==0, N%128==0, K%8==0 (true for all shapes here).
// ---------------------------------------------------------------------------
__global__ __launch_bounds__(256)
void sgemm_bias(const float* __restrict__ A, const float* __restrict__ B,
                const float* __restrict__ bias, float* __restrict__ C,
                int M, int N, int K)
{
    const int BM = 128, BN = 128, BK = 8;
    __shared__ float As[BK][BM];   // A stored transposed for stride-1 frag loads
    __shared__ float Bs[BK][BN];

    int tid = threadIdx.x;
    int tx  = tid & 15;            // 0..15  -> column group
    int ty  = tid >> 4;            // 0..15  -> row group
    int a_row = tid >> 1;          // 0..127
    int a_col = (tid & 1) * 4;     // 0 or 4
    int b_row = tid >> 5;          // 0..7
    int b_col = (tid & 31) * 4;    // 0..124

    const float* Ab = A + (size_t)blockIdx.y * BM * K;
    const float* Bb = B + (size_t)blockIdx.x * BN;

    float acc[8][8];
#pragma unroll
    for (int i = 0; i < 8; i++)
#pragma unroll
        for (int j = 0; j < 8; j++) acc[i][j] = 0.f;

    for (int k0 = 0; k0 < K; k0 += BK) {
        float4 av = *(const float4*)(Ab + (size_t)a_row * K + k0 + a_col);
        As[a_col + 0][a_row] = av.x;
        As[a_col + 1][a_row] = av.y;
        As[a_col + 2][a_row] = av.z;
        As[a_col + 3][a_row] = av.w;
        *(float4*)&Bs[b_row][b_col] =
            *(const float4*)(Bb + (size_t)(k0 + b_row) * N + b_col);
        __syncthreads();

#pragma unroll
        for (int kk = 0; kk < BK; kk++) {
            float af[8], bf[8];
            *(float4*)&af[0] = *(const float4*)&As[kk][ty * 8];
            *(float4*)&af[4] = *(const float4*)&As[kk][ty * 8 + 4];
            *(float4*)&bf[0] = *(const float4*)&Bs[kk][tx * 8];
            *(float4*)&bf[4] = *(const float4*)&Bs[kk][tx * 8 + 4];
#pragma unroll
            for (int i = 0; i < 8; i++)
#pragma unroll
                for (int j = 0; j < 8; j++)
                    acc[i][j] = fmaf(af[i], bf[j], acc[i][j]);
        }
        __syncthreads();
    }

    int crow = blockIdx.y * BM + ty * 8;
    int ccol = blockIdx.x * BN + tx * 8;
    float4 b0 = *(const float4*)(bias + ccol);
    float4 b1 = *(const float4*)(bias + ccol + 4);
#pragma unroll
    for (int i = 0; i < 8; i++) {
        float4 c0 = make_float4(acc[i][0] + b0.x, acc[i][1] + b0.y,
                                acc[i][2] + b0.z, acc[i][3] + b0.w);
        float4 c1 = make_float4(acc[i][4] + b1.x, acc[i][5] + b1.y,
                                acc[i][6] + b1.z, acc[i][7] + b1.w);
        *(float4*)(C + (size_t)(crow + i) * N + ccol)     = c0;
        *(float4*)(C + (size_t)(crow + i) * N + ccol + 4) = c1;
    }
}

// ---------------------------------------------------------------------------
// Flash-style causal attention over qkv buffer [B,S,3E] (q|k|v in last dim).
// Block = 64 threads = 64 queries. Q row + accumulator in registers.
// K/V tiles (64x64) + score tile in SMEM (48 KB). Online softmax.
// grid = (S/64, B*H)
// ---------------------------------------------------------------------------
__global__ __launch_bounds__(64)
void attn_kernel(const float* __restrict__ qkv, float* __restrict__ out)
{
    __shared__ float smem[3 * 64 * 64];
    float* Ks = smem;               // [k][d] 64x64
    float* Vs = smem + 4096;        // [k][d]
    float* Ps = smem + 8192;        // [k][q] (key-major: conflict-free)

    int tid = threadIdx.x;
    int qt  = blockIdx.x;
    int bh  = blockIdx.y;
    int b = bh >> 4, h = bh & 15;
    const int RS = 3 * EMBED;       // row stride of qkv
    const float* base = qkv + (size_t)b * SEQ * RS + h * HDIM;
    int q0 = qt * 64;

    // Q row of this thread's query -> registers (16 x float4)
    float4 qr[16];
    {
        const float* qrow = base + (size_t)(q0 + tid) * RS;
#pragma unroll
        for (int i = 0; i < 16; i++) qr[i] = *(const float4*)(qrow + i * 4);
    }

    float m = -1e30f, l = 0.f;
    float4 o[16];
#pragma unroll
    for (int i = 0; i < 16; i++) o[i] = make_float4(0.f, 0.f, 0.f, 0.f);

    for (int kt = 0; kt <= qt; ++kt) {
        int k0 = kt * 64;
        // cooperative K/V tile load: 1024 float4 across 64 threads
#pragma unroll
        for (int i = 0; i < 16; i++) {
            int idx = i * 64 + tid;
            int r = idx >> 4;
            int c = (idx & 15) * 4;
            size_t go = (size_t)(k0 + r) * RS + c;
            ((float4*)Ks)[idx] = *(const float4*)(base + EMBED + go);
            ((float4*)Vs)[idx] = *(const float4*)(base + 2 * EMBED + go);
        }
        __syncthreads();

        int kmax = (kt == qt) ? tid : 63;   // causal mask only on diagonal tile
        float tmax = -1e30f;
        for (int k = 0; k < 64; k++) {
            const float4* kr = (const float4*)(Ks + k * 64);
            float a0 = 0.f, a1 = 0.f, a2 = 0.f, a3 = 0.f;
#pragma unroll
            for (int i = 0; i < 16; i += 4) {
                float4 k0v = kr[i], k1v = kr[i + 1], k2v = kr[i + 2], k3v = kr[i + 3];
                a0 += qr[i].x     * k0v.x + qr[i].y     * k0v.y + qr[i].z     * k0v.z + qr[i].w     * k0v.w;
                a1 += qr[i + 1].x * k1v.x + qr[i + 1].y * k1v.y + qr[i + 1].z * k1v.z + qr[i + 1].w * k1v.w;
                a2 += qr[i + 2].x * k2v.x + qr[i + 2].y * k2v.y + qr[i + 2].z * k2v.z + qr[i + 2].w * k2v.w;
                a3 += qr[i + 3].x * k3v.x + qr[i + 3].y * k3v.y + qr[i + 3].z * k3v.z + qr[i + 3].w * k3v.w;
            }
            float s = (k <= kmax) ? (a0 + a1 + a2 + a3) * 0.125f : -1e30f;
            tmax = fmaxf(tmax, s);
            Ps[k * 64 + tid] = s;
        }

        float m_new = fmaxf(m, tmax);
        float alpha = __expf(m - m_new);
        l *= alpha;
#pragma unroll
        for (int i = 0; i < 16; i++) {
            o[i].x *= alpha; o[i].y *= alpha; o[i].z *= alpha; o[i].w *= alpha;
        }
        for (int k = 0; k < 64; k++) {
            float p = __expf(Ps[k * 64 + tid] - m_new);
            l += p;
            const float4* vr = (const float4*)(Vs + k * 64);
#pragma unroll
            for (int i = 0; i < 16; i++) {
                float4 vv = vr[i];
                o[i].x = fmaf(p, vv.x, o[i].x);
                o[i].y = fmaf(p, vv.y, o[i].y);
                o[i].z = fmaf(p, vv.z, o[i].z);
                o[i].w = fmaf(p, vv.w, o[i].w);
            }
        }
        m = m_new;
        __syncthreads();
    }

    // stage output through smem (pitch 65 -> conflict-free), then coalesced store
    float inv_l = 1.f / l;
    float* sm = smem;  // reuse Ks/Vs region (64*65 = 4160 floats fits in 8192)
#pragma unroll
    for (int i = 0; i < 16; i++) {
        sm[tid * 65 + i * 4 + 0] = o[i].x * inv_l;
        sm[tid * 65 + i * 4 + 1] = o[i].y * inv_l;
        sm[tid * 65 + i * 4 + 2] = o[i].z * inv_l;
        sm[tid * 65 + i * 4 + 3] = o[i].w * inv_l;
    }
    __syncthreads();
    float* ob = out + (size_t)(b * SEQ + q0) * EMBED + h * HDIM;
    for (int r = 0; r < 64; r++)
        ob[(size_t)r * EMBED + tid] = sm[r * 65 + tid];
}

// ---------------------------------------------------------------------------
extern "C" void kernel_launch(void* const* d_in, const int* in_sizes, int n_in,
                              void* d_out, int out_size)
{
    const float* hs     = (const float*)d_in[0];
    const float* attn_w = (const float*)d_in[1];
    const float* attn_b = (const float*)d_in[2];
    const float* proj_w = (const float*)d_in[3];
    const float* proj_b = (const float*)d_in[4];
    float* out = (float*)d_out;

    float* qkv;
    float* attn;
    cudaGetSymbolAddress((void**)&qkv,  g_qkv);
    cudaGetSymbolAddress((void**)&attn, g_attn);

    // 1) QKV projection: [8192,1024] @ [1024,3072] + b
    dim3 g1(3 * EMBED / 128, BATCH * SEQ / 128);
    sgemm_bias<<<g1, 256>>>(hs, attn_w, attn_b, qkv, BATCH * SEQ, 3 * EMBED, EMBED);

    // 2) causal flash attention -> [B,S,E] merged heads
    dim3 g2(SEQ / 64, BATCH * HEADS);
    attn_kernel<<<g2, 64>>>(qkv, attn);

    // 3) output projection: [8192,1024] @ [1024,1024] + b
    dim3 g3(EMBED / 128, BATCH * SEQ / 128);
    sgemm_bias<<<g3, 256>>>(attn, proj_w, proj_b, out, BATCH * SEQ, EMBED, EMBED);
}

// round 3
// speedup vs baseline: 1.4502x; 1.4502x over previous
#include <cuda_runtime.h>
#include <cuda_bf16.h>
#include <cstdint>

#define EMBED 1024
#define SEQ   2048
#define BATCH 4
#define HEADS 16
#define HDIM  64
#define MTOT  (BATCH * SEQ)          // 8192 rows

// ---------------- scratch (static device globals; allocation-free) ----------
__device__ float          g_qkv[(size_t)MTOT * 3 * EMBED];      // fp32 qkv
__device__ __nv_bfloat16  g_Ah[(size_t)MTOT * EMBED];           // hs split hi
__device__ __nv_bfloat16  g_Al[(size_t)MTOT * EMBED];           // hs split lo
__device__ __nv_bfloat16  g_Wqh[(size_t)3 * EMBED * EMBED];     // qkv W^T hi [N][K]
__device__ __nv_bfloat16  g_Wql[(size_t)3 * EMBED * EMBED];
__device__ __nv_bfloat16  g_Wph[(size_t)EMBED * EMBED];         // proj W^T hi
__device__ __nv_bfloat16  g_Wpl[(size_t)EMBED * EMBED];
__device__ __nv_bfloat16  g_Xh[(size_t)MTOT * EMBED];           // attn out hi
__device__ __nv_bfloat16  g_Xl[(size_t)MTOT * EMBED];           // attn out lo

// ---------------- helpers ----------------------------------------------------
__device__ __forceinline__ uint32_t smem_u32(const void* p) {
    uint32_t a;
    asm("{ .reg .u64 t; cvta.to.shared.u64 t, %1; cvt.u32.u64 %0, t; }" : "=r"(a) : "l"(p));
    return a;
}
#define CP_ASYNC16(dst, src) \
    asm volatile("cp.async.cg.shared.global [%0], [%1], 16;" :: "r"(dst), "l"(src))
#define CP_COMMIT() asm volatile("cp.async.commit_group;")
#define CP_WAIT(n)  asm volatile("cp.async.wait_group %0;" :: "n"(n))

__device__ __forceinline__ void ldsm_x4(uint32_t* r, uint32_t addr) {
    asm volatile("ldmatrix.sync.aligned.m8n8.x4.shared.b16 {%0,%1,%2,%3}, [%4];"
                 : "=r"(r[0]), "=r"(r[1]), "=r"(r[2]), "=r"(r[3]) : "r"(addr));
}
__device__ __forceinline__ void ldsm_x2(uint32_t* r, uint32_t addr) {
    asm volatile("ldmatrix.sync.aligned.m8n8.x2.shared.b16 {%0,%1}, [%2];"
                 : "=r"(r[0]), "=r"(r[1]) : "r"(addr));
}
__device__ __forceinline__ void mma_bf16(float* d, const uint32_t* a, const uint32_t* b) {
    asm volatile("mma.sync.aligned.m16n8k16.row.col.f32.bf16.bf16.f32 "
                 "{%0,%1,%2,%3}, {%4,%5,%6,%7}, {%8,%9}, {%0,%1,%2,%3};"
                 : "+f"(d[0]), "+f"(d[1]), "+f"(d[2]), "+f"(d[3])
                 : "r"(a[0]), "r"(a[1]), "r"(a[2]), "r"(a[3]), "r"(b[0]), "r"(b[1]));
}

// ---------------------------------------------------------------------------
// split fp32 -> bf16 hi/lo
// ---------------------------------------------------------------------------
__global__ void split_f32(const float* __restrict__ x, __nv_bfloat16* __restrict__ hi,
                          __nv_bfloat16* __restrict__ lo, int n4)
{
    int i = blockIdx.x * blockDim.x + threadIdx.x;
    int stride = gridDim.x * blockDim.x;
    for (; i < n4; i += stride) {
        float4 v = ((const float4*)x)[i];
        __nv_bfloat16 h0 = __float2bfloat16(v.x), h1 = __float2bfloat16(v.y);
        __nv_bfloat16 h2 = __float2bfloat16(v.z), h3 = __float2bfloat16(v.w);
        __nv_bfloat16 l0 = __float2bfloat16(v.x - __bfloat162float(h0));
        __nv_bfloat16 l1 = __float2bfloat16(v.y - __bfloat162float(h1));
        __nv_bfloat16 l2 = __float2bfloat16(v.z - __bfloat162float(h2));
        __nv_bfloat16 l3 = __float2bfloat16(v.w - __bfloat162float(h3));
        ((ushort4*)hi)[i] = make_ushort4(__bfloat16_as_ushort(h0), __bfloat16_as_ushort(h1),
                                         __bfloat16_as_ushort(h2), __bfloat16_as_ushort(h3));
        ((ushort4*)lo)[i] = make_ushort4(__bfloat16_as_ushort(l0), __bfloat16_as_ushort(l1),
                                         __bfloat16_as_ushort(l2), __bfloat16_as_ushort(l3));
    }
}

// ---------------------------------------------------------------------------
// transpose + split: W[K][N] fp32 -> Wt_hi/lo[N][K] bf16
// ---------------------------------------------------------------------------
__global__ void transpose_split(const float* __restrict__ W, __nv_bfloat16* __restrict__ Th,
                                __nv_bfloat16* __restrict__ Tl, int K, int N)
{
    __shared__ float t[32][33];
    int tx = threadIdx.x, ty = threadIdx.y;
#pragma unroll
    for (int j = 0; j < 4; j++) {
        int k = blockIdx.y * 32 + ty + j * 8;
        int n = blockIdx.x * 32 + tx;
        t[ty + j * 8][tx] = W[(size_t)k * N + n];
    }
    __syncthreads();
#pragma unroll
    for (int j = 0; j < 4; j++) {
        int n = blockIdx.x * 32 + ty + j * 8;
        int k = blockIdx.y * 32 + tx;
        float v = t[tx][ty + j * 8];
        __nv_bfloat16 h = __float2bfloat16(v);
        __nv_bfloat16 l = __float2bfloat16(v - __bfloat162float(h));
        Th[(size_t)n * K + k] = h;
        Tl[(size_t)n * K + k] = l;
    }
}

// ---------------------------------------------------------------------------
// bf16-split HMMA GEMM: C[M,N] = A[M,K] @ Bt[N,K]^T + bias
// block tile 128x128x32, 256 thr (8 warps, 2x4), warp tile 64x32
// smem per stage: 4 tiles (Ah,Al,Bh,Bl) of 128x32 bf16 = 8KB each -> 32KB; 2 stages
// smem layout per tile row: 64B (4 x 16B chunks), chunk swizzle c ^ ((r>>1)&3)
// ---------------------------------------------------------------------------
#define GSTAGE 32768
#define GTILE  8192

__device__ __forceinline__ void gemm_load_stage(
    const __nv_bfloat16* __restrict__ Ah, const __nv_bfloat16* __restrict__ Al,
    const __nv_bfloat16* __restrict__ Bh, const __nv_bfloat16* __restrict__ Bl,
    int K, int k0, uint32_t sdst, int tid)
{
    const __nv_bfloat16* srcs[4] = { Ah, Al, Bh, Bl };
#pragma unroll
    for (int i = 0; i < 8; i++) {
        int idx = i * 256 + tid;          // 0..2047
        int tile = idx >> 9;              // 0..3
        int r    = (idx >> 2) & 127;
        int c    = idx & 3;
        const char* g = (const char*)(srcs[tile] + (size_t)r * K + k0) + c * 16;
        uint32_t s = sdst + tile * GTILE + r * 64 + ((c ^ ((r >> 1) & 3)) << 4);
        CP_ASYNC16(s, g);
    }
}

__global__ __launch_bounds__(256)
void gemm_hmma(const __nv_bfloat16* __restrict__ Ah, const __nv_bfloat16* __restrict__ Al,
               const __nv_bfloat16* __restrict__ Bh, const __nv_bfloat16* __restrict__ Bl,
               const float* __restrict__ bias, float* __restrict__ C, int N, int K)
{
    extern __shared__ char smem[];
    uint32_t sb = smem_u32(smem);
    const int tid  = threadIdx.x;
    const int warp = tid >> 5, lane = tid & 31;
    const int wm = warp >> 2, wn = warp & 3;          // 2 x 4 warp grid

    const int m0 = blockIdx.y * 128;
    const int n0 = blockIdx.x * 128;
    const __nv_bfloat16* Ah0 = Ah + (size_t)m0 * K;
    const __nv_bfloat16* Al0 = Al + (size_t)m0 * K;
    const __nv_bfloat16* Bh0 = Bh + (size_t)n0 * K;
    const __nv_bfloat16* Bl0 = Bl + (size_t)n0 * K;

    float acc[4][4][4];
#pragma unroll
    for (int i = 0; i < 4; i++)
#pragma unroll
        for (int j = 0; j < 4; j++)
#pragma unroll
            for (int k = 0; k < 4; k++) acc[i][j][k] = 0.f;

    const int iters = K >> 5;
    gemm_load_stage(Ah0, Al0, Bh0, Bl0, K, 0, sb, tid);
    CP_COMMIT();

    // precomputed ldmatrix lane addressing
    const int a_r = lane & 15;            // row within m16
    const int a_h = lane >> 4;            // k-chunk half (0/1)
    const int b_r = lane & 7;             // row within n8
    const int b_h = (lane >> 3) & 1;      // k-chunk half

    for (int it = 0; it < iters; ++it) {
        uint32_t sbuf = sb + (it & 1) * GSTAGE;
        if (it + 1 < iters) {
            gemm_load_stage(Ah0, Al0, Bh0, Bl0, K, (it + 1) * 32,
                            sb + ((it + 1) & 1) * GSTAGE, tid);
            CP_COMMIT();
            CP_WAIT(1);
        } else {
            CP_WAIT(0);
        }
        __syncthreads();

#pragma unroll
        for (int s = 0; s < 2; s++) {
            uint32_t ah[4][4], al[4][4];
#pragma unroll
            for (int mi = 0; mi < 4; mi++) {
                int row = wm * 64 + mi * 16 + a_r;
                int ch  = s * 2 + a_h;
                uint32_t off = row * 64 + ((ch ^ ((row >> 1) & 3)) << 4);
                ldsm_x4(ah[mi], sbuf + 0 * GTILE + off);
                ldsm_x4(al[mi], sbuf + 1 * GTILE + off);
            }
            uint32_t bh[4][2], bl[4][2];
#pragma unroll
            for (int ni = 0; ni < 4; ni++) {
                int row = wn * 32 + ni * 8 + b_r;
                int ch  = s * 2 + b_h;
                uint32_t off = row * 64 + ((ch ^ ((row >> 1) & 3)) << 4);
                ldsm_x2(bh[ni], sbuf + 2 * GTILE + off);
                ldsm_x2(bl[ni], sbuf + 3 * GTILE + off);
            }
#pragma unroll
            for (int mi = 0; mi < 4; mi++)
#pragma unroll
                for (int ni = 0; ni < 4; ni++) {
                    mma_bf16(acc[mi][ni], ah[mi], bh[ni]);
                    mma_bf16(acc[mi][ni], ah[mi], bl[ni]);
                    mma_bf16(acc[mi][ni], al[mi], bh[ni]);
                }
        }
        __syncthreads();
    }

    // epilogue: registers -> global, + bias
    const int r0 = lane >> 2;
    const int c0 = (lane & 3) * 2;
#pragma unroll
    for (int ni = 0; ni < 4; ni++) {
        int col = n0 + wn * 32 + ni * 8 + c0;
        float2 bv = *(const float2*)(bias + col);
#pragma unroll
        for (int mi = 0; mi < 4; mi++) {
            int row = m0 + wm * 64 + mi * 16 + r0;
            float2 v0 = make_float2(acc[mi][ni][0] + bv.x, acc[mi][ni][1] + bv.y);
            float2 v1 = make_float2(acc[mi][ni][2] + bv.x, acc[mi][ni][3] + bv.y);
            *(float2*)(C + (size_t)row * N + col)       = v0;
            *(float2*)(C + (size_t)(row + 8) * N + col) = v1;
        }
    }
}

// ---------------------------------------------------------------------------
// Flash-style causal attention (fp32). Emits hi/lo bf16 split for proj GEMM.
// ---------------------------------------------------------------------------
__global__ __launch_bounds__(64)
void attn_kernel(const float* __restrict__ qkv,
                 __nv_bfloat16* __restrict__ out_hi, __nv_bfloat16* __restrict__ out_lo)
{
    __shared__ float smem[3 * 64 * 64];
    float* Ks = smem;
    float* Vs = smem + 4096;
    float* Ps = smem + 8192;

    int tid = threadIdx.x;
    int qt  = blockIdx.x;
    int bh  = blockIdx.y;
    int b = bh >> 4, h = bh & 15;
    const int RS = 3 * EMBED;
    const float* base = qkv + (size_t)b * SEQ * RS + h * HDIM;
    int q0 = qt * 64;

    float4 qr[16];
    {
        const float* qrow = base + (size_t)(q0 + tid) * RS;
#pragma unroll
        for (int i = 0; i < 16; i++) qr[i] = *(const float4*)(qrow + i * 4);
    }

    float m = -1e30f, l = 0.f;
    float4 o[16];
#pragma unroll
    for (int i = 0; i < 16; i++) o[i] = make_float4(0.f, 0.f, 0.f, 0.f);

    for (int kt = 0; kt <= qt; ++kt) {
        int k0 = kt * 64;
#pragma unroll
        for (int i = 0; i < 16; i++) {
            int idx = i * 64 + tid;
            int r = idx >> 4;
            int c = (idx & 15) * 4;
            size_t go = (size_t)(k0 + r) * RS + c;
            ((float4*)Ks)[idx] = *(const float4*)(base + EMBED + go);
            ((float4*)Vs)[idx] = *(const float4*)(base + 2 * EMBED + go);
        }
        __syncthreads();

        int kmax = (kt == qt) ? tid : 63;
        float tmax = -1e30f;
        for (int k = 0; k < 64; k++) {
            const float4* kr = (const float4*)(Ks + k * 64);
            float a0 = 0.f, a1 = 0.f, a2 = 0.f, a3 = 0.f;
#pragma unroll
            for (int i = 0; i < 16; i += 4) {
                float4 k0v = kr[i], k1v = kr[i + 1], k2v = kr[i + 2], k3v = kr[i + 3];
                a0 += qr[i].x     * k0v.x + qr[i].y     * k0v.y + qr[i].z     * k0v.z + qr[i].w     * k0v.w;
                a1 += qr[i + 1].x * k1v.x + qr[i + 1].y * k1v.y + qr[i + 1].z * k1v.z + qr[i + 1].w * k1v.w;
                a2 += qr[i + 2].x * k2v.x + qr[i + 2].y * k2v.y + qr[i + 2].z * k2v.z + qr[i + 2].w * k2v.w;
                a3 += qr[i + 3].x * k3v.x + qr[i + 3].y * k3v.y + qr[i + 3].z * k3v.z + qr[i + 3].w * k3v.w;
            }
            float s = (k <= kmax) ? (a0 + a1 + a2 + a3) * 0.125f : -1e30f;
            tmax = fmaxf(tmax, s);
            Ps[k * 64 + tid] = s;
        }

        float m_new = fmaxf(m, tmax);
        float alpha = __expf(m - m_new);
        l *= alpha;
#pragma unroll
        for (int i = 0; i < 16; i++) {
            o[i].x *= alpha; o[i].y *= alpha; o[i].z *= alpha; o[i].w *= alpha;
        }
        for (int k = 0; k < 64; k++) {
            float p = __expf(Ps[k * 64 + tid] - m_new);
            l += p;
            const float4* vr = (const float4*)(Vs + k * 64);
#pragma unroll
            for (int i = 0; i < 16; i++) {
                float4 vv = vr[i];
                o[i].x = fmaf(p, vv.x, o[i].x);
                o[i].y = fmaf(p, vv.y, o[i].y);
                o[i].z = fmaf(p, vv.z, o[i].z);
                o[i].w = fmaf(p, vv.w, o[i].w);
            }
        }
        m = m_new;
        __syncthreads();
    }

    float inv_l = 1.f / l;
    float* sm = smem;
#pragma unroll
    for (int i = 0; i < 16; i++) {
        sm[tid * 65 + i * 4 + 0] = o[i].x * inv_l;
        sm[tid * 65 + i * 4 + 1] = o[i].y * inv_l;
        sm[tid * 65 + i * 4 + 2] = o[i].z * inv_l;
        sm[tid * 65 + i * 4 + 3] = o[i].w * inv_l;
    }
    __syncthreads();
    size_t obase = (size_t)(b * SEQ + q0) * EMBED + h * HDIM;
    for (int r = 0; r < 64; r++) {
        float v = sm[r * 65 + tid];
        __nv_bfloat16 hh = __float2bfloat16(v);
        __nv_bfloat16 ll = __float2bfloat16(v - __bfloat162float(hh));
        out_hi[obase + (size_t)r * EMBED + tid] = hh;
        out_lo[obase + (size_t)r * EMBED + tid] = ll;
    }
}

// ---------------------------------------------------------------------------
extern "C" void kernel_launch(void* const* d_in, const int* in_sizes, int n_in,
                              void* d_out, int out_size)
{
    const float* hs     = (const float*)d_in[0];
    const float* attn_w = (const float*)d_in[1];
    const float* attn_b = (const float*)d_in[2];
    const float* proj_w = (const float*)d_in[3];
    const float* proj_b = (const float*)d_in[4];
    float* out = (float*)d_out;

    float *qkv;
    __nv_bfloat16 *Ah, *Al, *Wqh, *Wql, *Wph, *Wpl, *Xh, *Xl;
    cudaGetSymbolAddress((void**)&qkv, g_qkv);
    cudaGetSymbolAddress((void**)&Ah,  g_Ah);
    cudaGetSymbolAddress((void**)&Al,  g_Al);
    cudaGetSymbolAddress((void**)&Wqh, g_Wqh);
    cudaGetSymbolAddress((void**)&Wql, g_Wql);
    cudaGetSymbolAddress((void**)&Wph, g_Wph);
    cudaGetSymbolAddress((void**)&Wpl, g_Wpl);
    cudaGetSymbolAddress((void**)&Xh,  g_Xh);
    cudaGetSymbolAddress((void**)&Xl,  g_Xl);

    cudaFuncSetAttribute(gemm_hmma, cudaFuncAttributeMaxDynamicSharedMemorySize, 2 * GSTAGE);

    // 0) prepare bf16-split operands
    split_f32<<<2048, 256>>>(hs, Ah, Al, MTOT * EMBED / 4);
    transpose_split<<<dim3(3 * EMBED / 32, EMBED / 32), dim3(32, 8)>>>(attn_w, Wqh, Wql, EMBED, 3 * EMBED);
    transpose_split<<<dim3(EMBED / 32, EMBED / 32), dim3(32, 8)>>>(proj_w, Wph, Wpl, EMBED, EMBED);

    // 1) QKV projection (HMMA): [8192,1024] x [1024,3072] + b
    gemm_hmma<<<dim3(3 * EMBED / 128, MTOT / 128), 256, 2 * GSTAGE>>>(Ah, Al, Wqh, Wql, attn_b, qkv, 3 * EMBED, EMBED);

    // 2) causal flash attention -> split bf16 [B,S,E]
    attn_kernel<<<dim3(SEQ / 64, BATCH * HEADS), 64>>>(qkv, Xh, Xl);

    // 3) output projection (HMMA): [8192,1024] x [1024,1024] + b
    gemm_hmma<<<dim3(EMBED / 128, MTOT / 128), 256, 2 * GSTAGE>>>(Xh, Xl, Wph, Wpl, proj_b, out, EMBED, EMBED);
}

// round 6
// speedup vs baseline: 3.5669x; 2.4596x over previous
#include <cuda_runtime.h>
#include <cuda_bf16.h>
#include <cstdint>

#define EMBED 1024
#define SEQ   2048
#define BATCH 4
#define HEADS 16
#define HDIM  64
#define MTOT  (BATCH * SEQ)          // 8192 rows
#define RSQKV (3 * EMBED)            // qkv row stride (elements)

// ---------------- scratch (static device globals; allocation-free) ----------
__device__ __nv_bfloat16  g_Ah[(size_t)MTOT * EMBED];           // hs split hi
__device__ __nv_bfloat16  g_Al[(size_t)MTOT * EMBED];           // hs split lo
__device__ __nv_bfloat16  g_Wqh[(size_t)3 * EMBED * EMBED];     // qkv W^T hi [N][K]
__device__ __nv_bfloat16  g_Wql[(size_t)3 * EMBED * EMBED];
__device__ __nv_bfloat16  g_Wph[(size_t)EMBED * EMBED];         // proj W^T hi
__device__ __nv_bfloat16  g_Wpl[(size_t)EMBED * EMBED];
__device__ __nv_bfloat16  g_QKVh[(size_t)MTOT * 3 * EMBED];     // qkv split hi
__device__ __nv_bfloat16  g_QKVl[(size_t)MTOT * 3 * EMBED];     // qkv split lo
__device__ __nv_bfloat16  g_Xh[(size_t)MTOT * EMBED];           // attn out hi
__device__ __nv_bfloat16  g_Xl[(size_t)MTOT * EMBED];           // attn out lo

// ---------------- helpers ----------------------------------------------------
__device__ __forceinline__ uint32_t smem_u32(const void* p) {
    uint32_t a;
    asm("{ .reg .u64 t; cvta.to.shared.u64 t, %1; cvt.u32.u64 %0, t; }" : "=r"(a) : "l"(p));
    return a;
}
#define CP_ASYNC16(dst, src) \
    asm volatile("cp.async.cg.shared.global [%0], [%1], 16;" :: "r"(dst), "l"(src))
#define CP_COMMIT() asm volatile("cp.async.commit_group;")
#define CP_WAIT(n)  asm volatile("cp.async.wait_group %0;" :: "n"(n))

__device__ __forceinline__ void ldsm_x4(uint32_t* r, uint32_t addr) {
    asm volatile("ldmatrix.sync.aligned.m8n8.x4.shared.b16 {%0,%1,%2,%3}, [%4];"
                 : "=r"(r[0]), "=r"(r[1]), "=r"(r[2]), "=r"(r[3]) : "r"(addr));
}
__device__ __forceinline__ void ldsm_x2(uint32_t* r, uint32_t addr) {
    asm volatile("ldmatrix.sync.aligned.m8n8.x2.shared.b16 {%0,%1}, [%2];"
                 : "=r"(r[0]), "=r"(r[1]) : "r"(addr));
}
__device__ __forceinline__ void ldsm_x2_t(uint32_t* r, uint32_t addr) {
    asm volatile("ldmatrix.sync.aligned.m8n8.x2.trans.shared.b16 {%0,%1}, [%2];"
                 : "=r"(r[0]), "=r"(r[1]) : "r"(addr));
}
__device__ __forceinline__ void mma_bf16(float* d, const uint32_t* a, const uint32_t* b) {
    asm volatile("mma.sync.aligned.m16n8k16.row.col.f32.bf16.bf16.f32 "
                 "{%0,%1,%2,%3}, {%4,%5,%6,%7}, {%8,%9}, {%0,%1,%2,%3};"
                 : "+f"(d[0]), "+f"(d[1]), "+f"(d[2]), "+f"(d[3])
                 : "r"(a[0]), "r"(a[1]), "r"(a[2]), "r"(a[3]), "r"(b[0]), "r"(b[1]));
}
__device__ __forceinline__ float ex2f(float x) {
    float y; asm("ex2.approx.f32 %0, %1;" : "=f"(y) : "f"(x)); return y;
}
// pack {lo=a, hi=b} fp32 -> bf16x2
__device__ __forceinline__ uint32_t pack_bf2(float a, float b) {
    uint32_t r; asm("cvt.rn.bf16x2.f32 %0, %1, %2;" : "=r"(r) : "f"(b), "f"(a)); return r;
}
__device__ __forceinline__ float bf16_rt(float v) {   // round-trip through bf16
    return __bfloat162float(__float2bfloat16(v));
}

// ---------------------------------------------------------------------------
// split fp32 -> bf16 hi/lo
// ---------------------------------------------------------------------------
__global__ void split_f32(const float* __restrict__ x, __nv_bfloat16* __restrict__ hi,
                          __nv_bfloat16* __restrict__ lo, int n4)
{
    int i = blockIdx.x * blockDim.x + threadIdx.x;
    int stride = gridDim.x * blockDim.x;
    for (; i < n4; i += stride) {
        float4 v = ((const float4*)x)[i];
        __nv_bfloat16 h0 = __float2bfloat16(v.x), h1 = __float2bfloat16(v.y);
        __nv_bfloat16 h2 = __float2bfloat16(v.z), h3 = __float2bfloat16(v.w);
        __nv_bfloat16 l0 = __float2bfloat16(v.x - __bfloat162float(h0));
        __nv_bfloat16 l1 = __float2bfloat16(v.y - __bfloat162float(h1));
        __nv_bfloat16 l2 = __float2bfloat16(v.z - __bfloat162float(h2));
        __nv_bfloat16 l3 = __float2bfloat16(v.w - __bfloat162float(h3));
        ((ushort4*)hi)[i] = make_ushort4(__bfloat16_as_ushort(h0), __bfloat16_as_ushort(h1),
                                         __bfloat16_as_ushort(h2), __bfloat16_as_ushort(h3));
        ((ushort4*)lo)[i] = make_ushort4(__bfloat16_as_ushort(l0), __bfloat16_as_ushort(l1),
                                         __bfloat16_as_ushort(l2), __bfloat16_as_ushort(l3));
    }
}

// ---------------------------------------------------------------------------
// transpose + split: W[K][N] fp32 -> Wt_hi/lo[N][K] bf16
// ---------------------------------------------------------------------------
__global__ void transpose_split(const float* __restrict__ W, __nv_bfloat16* __restrict__ Th,
                                __nv_bfloat16* __restrict__ Tl, int K, int N)
{
    __shared__ float t[32][33];
    int tx = threadIdx.x, ty = threadIdx.y;
#pragma unroll
    for (int j = 0; j < 4; j++) {
        int k = blockIdx.y * 32 + ty + j * 8;
        int n = blockIdx.x * 32 + tx;
        t[ty + j * 8][tx] = W[(size_t)k * N + n];
    }
    __syncthreads();
#pragma unroll
    for (int j = 0; j < 4; j++) {
        int n = blockIdx.x * 32 + ty + j * 8;
        int k = blockIdx.y * 32 + tx;
        float v = t[tx][ty + j * 8];
        __nv_bfloat16 h = __float2bfloat16(v);
        __nv_bfloat16 l = __float2bfloat16(v - __bfloat162float(h));
        Th[(size_t)n * K + k] = h;
        Tl[(size_t)n * K + k] = l;
    }
}

// ---------------------------------------------------------------------------
// bf16-split HMMA GEMM core. block 128x128x32, 256 thr, warp tile 64x32.
// EPI=0: fp32 out + bias.  EPI=1: bf16 hi/lo split out + bias.
// ---------------------------------------------------------------------------
#define GSTAGE 32768
#define GTILE  8192

__device__ __forceinline__ void gemm_load_stage(
    const __nv_bfloat16* __restrict__ Ah, const __nv_bfloat16* __restrict__ Al,
    const __nv_bfloat16* __restrict__ Bh, const __nv_bfloat16* __restrict__ Bl,
    int K, int k0, uint32_t sdst, int tid)
{
    const __nv_bfloat16* srcs[4] = { Ah, Al, Bh, Bl };
#pragma unroll
    for (int i = 0; i < 8; i++) {
        int idx = i * 256 + tid;          // 0..2047
        int tile = idx >> 9;              // 0..3
        int r    = (idx >> 2) & 127;
        int c    = idx & 3;
        const char* g = (const char*)(srcs[tile] + (size_t)r * K + k0) + c * 16;
        uint32_t s = sdst + tile * GTILE + r * 64 + ((c ^ ((r >> 1) & 3)) << 4);
        CP_ASYNC16(s, g);
    }
}

template <int EPI>
__device__ __forceinline__ void gemm_body(
    const __nv_bfloat16* __restrict__ Ah, const __nv_bfloat16* __restrict__ Al,
    const __nv_bfloat16* __restrict__ Bh, const __nv_bfloat16* __restrict__ Bl,
    const float* __restrict__ bias, float* __restrict__ C,
    __nv_bfloat16* __restrict__ Ch, __nv_bfloat16* __restrict__ Cl, int N, int K)
{
    extern __shared__ char smem[];
    uint32_t sb = smem_u32(smem);
    const int tid  = threadIdx.x;
    const int warp = tid >> 5, lane = tid & 31;
    const int wm = warp >> 2, wn = warp & 3;

    const int m0 = blockIdx.y * 128;
    const int n0 = blockIdx.x * 128;
    const __nv_bfloat16* Ah0 = Ah + (size_t)m0 * K;
    const __nv_bfloat16* Al0 = Al + (size_t)m0 * K;
    const __nv_bfloat16* Bh0 = Bh + (size_t)n0 * K;
    const __nv_bfloat16* Bl0 = Bl + (size_t)n0 * K;

    float acc[4][4][4];
#pragma unroll
    for (int i = 0; i < 4; i++)
#pragma unroll
        for (int j = 0; j < 4; j++)
#pragma unroll
            for (int k = 0; k < 4; k++) acc[i][j][k] = 0.f;

    const int iters = K >> 5;
    gemm_load_stage(Ah0, Al0, Bh0, Bl0, K, 0, sb, tid);
    CP_COMMIT();

    const int a_r = lane & 15;
    const int a_h = lane >> 4;
    const int b_r = lane & 7;
    const int b_h = (lane >> 3) & 1;

    for (int it = 0; it < iters; ++it) {
        uint32_t sbuf = sb + (it & 1) * GSTAGE;
        if (it + 1 < iters) {
            gemm_load_stage(Ah0, Al0, Bh0, Bl0, K, (it + 1) * 32,
                            sb + ((it + 1) & 1) * GSTAGE, tid);
            CP_COMMIT();
            CP_WAIT(1);
        } else {
            CP_WAIT(0);
        }
        __syncthreads();

#pragma unroll
        for (int s = 0; s < 2; s++) {
            uint32_t ah[4][4], al[4][4];
#pragma unroll
            for (int mi = 0; mi < 4; mi++) {
                int row = wm * 64 + mi * 16 + a_r;
                int ch  = s * 2 + a_h;
                uint32_t off = row * 64 + ((ch ^ ((row >> 1) & 3)) << 4);
                ldsm_x4(ah[mi], sbuf + 0 * GTILE + off);
                ldsm_x4(al[mi], sbuf + 1 * GTILE + off);
            }
            uint32_t bh[4][2], bl[4][2];
#pragma unroll
            for (int ni = 0; ni < 4; ni++) {
                int row = wn * 32 + ni * 8 + b_r;
                int ch  = s * 2 + b_h;
                uint32_t off = row * 64 + ((ch ^ ((row >> 1) & 3)) << 4);
                ldsm_x2(bh[ni], sbuf + 2 * GTILE + off);
                ldsm_x2(bl[ni], sbuf + 3 * GTILE + off);
            }
#pragma unroll
            for (int mi = 0; mi < 4; mi++)
#pragma unroll
                for (int ni = 0; ni < 4; ni++) {
                    mma_bf16(acc[mi][ni], ah[mi], bh[ni]);
                    mma_bf16(acc[mi][ni], ah[mi], bl[ni]);
                    mma_bf16(acc[mi][ni], al[mi], bh[ni]);
                }
        }
        __syncthreads();
    }

    const int r0 = lane >> 2;
    const int c0 = (lane & 3) * 2;
#pragma unroll
    for (int ni = 0; ni < 4; ni++) {
        int col = n0 + wn * 32 + ni * 8 + c0;
        float2 bv = *(const float2*)(bias + col);
#pragma unroll
        for (int mi = 0; mi < 4; mi++) {
            int row = m0 + wm * 64 + mi * 16 + r0;
            float v00 = acc[mi][ni][0] + bv.x, v01 = acc[mi][ni][1] + bv.y;
            float v10 = acc[mi][ni][2] + bv.x, v11 = acc[mi][ni][3] + bv.y;
            if (EPI == 0) {
                *(float2*)(C + (size_t)row * N + col)       = make_float2(v00, v01);
                *(float2*)(C + (size_t)(row + 8) * N + col) = make_float2(v10, v11);
            } else {
                float h00 = bf16_rt(v00), h01 = bf16_rt(v01);
                float h10 = bf16_rt(v10), h11 = bf16_rt(v11);
                *(uint32_t*)(Ch + (size_t)row * N + col)       = pack_bf2(h00, h01);
                *(uint32_t*)(Ch + (size_t)(row + 8) * N + col) = pack_bf2(h10, h11);
                *(uint32_t*)(Cl + (size_t)row * N + col)       = pack_bf2(v00 - h00, v01 - h01);
                *(uint32_t*)(Cl + (size_t)(row + 8) * N + col) = pack_bf2(v10 - h10, v11 - h11);
            }
        }
    }
}

__global__ __launch_bounds__(256)
void gemm_hmma(const __nv_bfloat16* __restrict__ Ah, const __nv_bfloat16* __restrict__ Al,
               const __nv_bfloat16* __restrict__ Bh, const __nv_bfloat16* __restrict__ Bl,
               const float* __restrict__ bias, float* __restrict__ C, int N, int K)
{
    gemm_body<0>(Ah, Al, Bh, Bl, bias, C, nullptr, nullptr, N, K);
}
__global__ __launch_bounds__(256)
void gemm_hmma_split(const __nv_bfloat16* __restrict__ Ah, const __nv_bfloat16* __restrict__ Al,
                     const __nv_bfloat16* __restrict__ Bh, const __nv_bfloat16* __restrict__ Bl,
                     const float* __restrict__ bias,
                     __nv_bfloat16* __restrict__ Ch, __nv_bfloat16* __restrict__ Cl, int N, int K)
{
    gemm_body<1>(Ah, Al, Bh, Bl, bias, nullptr, Ch, Cl, N, K);
}

// ---------------------------------------------------------------------------
// HMMA flash attention, causal. Q tile 128 x 4 warps; K/V tiles 64, 2-stage.
// P is hi/lo split for the PV product (3-term) to keep rel_err ~1e-4.
// ---------------------------------------------------------------------------
#define ASQH 0
#define ASQL 16384
#define ASTG 32768
#define AKH  0
#define AKL  8192
#define AVH  16384
#define AVL  24576
#define ASMEM 98304
#define LOG2E_8 0.18033688f   // log2(e)/8

__device__ __forceinline__ void stage_kv(const __nv_bfloat16* kh, const __nv_bfloat16* kl,
                                         const __nv_bfloat16* vh, const __nv_bfloat16* vl,
                                         uint32_t sdst, int tid)
{
#pragma unroll
    for (int i = 0; i < 4; i++) {
        int idx = i * 128 + tid;      // 0..511
        int r = idx >> 3, c = idx & 7;
        uint32_t so = r * 128 + ((c ^ (r & 7)) << 4);
        size_t go = (size_t)r * RSQKV + c * 8;
        CP_ASYNC16(sdst + AKH + so, kh + go);
        CP_ASYNC16(sdst + AKL + so, kl + go);
        CP_ASYNC16(sdst + AVH + so, vh + go);
        CP_ASYNC16(sdst + AVL + so, vl + go);
    }
}

__global__ __launch_bounds__(128)
void attn_hmma(const __nv_bfloat16* __restrict__ qkvh, const __nv_bfloat16* __restrict__ qkvl,
               __nv_bfloat16* __restrict__ xh, __nv_bfloat16* __restrict__ xl)
{
    extern __shared__ char smem[];
    uint32_t sb = smem_u32(smem);
    const int tid = threadIdx.x, warp = tid >> 5, lane = tid & 31;
    const int qt = (int)(gridDim.x - 1) - (int)blockIdx.x;     // big tiles first
    const int bh = blockIdx.y;
    const int b = bh >> 4, h = bh & 15;
    const int q0 = qt * 128;

    const size_t bhoff = (size_t)b * SEQ * RSQKV + h * HDIM;
    const __nv_bfloat16* qh_g = qkvh + bhoff + (size_t)q0 * RSQKV;
    const __nv_bfloat16* ql_g = qkvl + bhoff + (size_t)q0 * RSQKV;
    const __nv_bfloat16* kh_g = qkvh + bhoff + EMBED;
    const __nv_bfloat16* kl_g = qkvl + bhoff + EMBED;
    const __nv_bfloat16* vh_g = qkvh + bhoff + 2 * EMBED;
    const __nv_bfloat16* vl_g = qkvl + bhoff + 2 * EMBED;

    // stage Q (hi+lo)
#pragma unroll
    for (int i = 0; i < 8; i++) {
        int idx = i * 128 + tid;
        int r = idx >> 3, c = idx & 7;
        uint32_t so = r * 128 + ((c ^ (r & 7)) << 4);
        size_t go = (size_t)r * RSQKV + c * 8;
        CP_ASYNC16(sb + ASQH + so, qh_g + go);
        CP_ASYNC16(sb + ASQL + so, ql_g + go);
    }
    CP_COMMIT();
    const int kts = 2 * qt + 2;
    stage_kv(kh_g, kl_g, vh_g, vl_g, sb + ASTG, tid);
    CP_COMMIT();

    CP_WAIT(1);                 // Q ready
    __syncthreads();

    // preload Qh fragments (reg-resident)
    uint32_t qfh[2][4][4];
#pragma unroll
    for (int mi = 0; mi < 2; mi++)
#pragma unroll
        for (int kc = 0; kc < 4; kc++) {
            int row = warp * 32 + mi * 16 + (lane & 15);
            int ch  = kc * 2 + (lane >> 4);
            ldsm_x4(qfh[mi][kc], sb + ASQH + row * 128 + ((ch ^ (row & 7)) << 4));
        }

    float m_s[2][2], l_s[2][2], O[2][8][4];
#pragma unroll
    for (int mi = 0; mi < 2; mi++)
#pragma unroll
        for (int hh = 0; hh < 2; hh++) { m_s[mi][hh] = -1e30f; l_s[mi][hh] = 0.f; }
#pragma unroll
    for (int mi = 0; mi < 2; mi++)
#pragma unroll
        for (int nd = 0; nd < 8; nd++)
#pragma unroll
            for (int e = 0; e < 4; e++) O[mi][nd][e] = 0.f;

    for (int kt = 0; kt < kts; ++kt) {
        uint32_t sbuf = sb + ASTG + (kt & 1) * 32768;
        if (kt == 0) { CP_WAIT(0); __syncthreads(); }
        if (kt + 1 < kts) {
            stage_kv(kh_g + (size_t)(kt + 1) * 64 * RSQKV, kl_g + (size_t)(kt + 1) * 64 * RSQKV,
                     vh_g + (size_t)(kt + 1) * 64 * RSQKV, vl_g + (size_t)(kt + 1) * 64 * RSQKV,
                     sb + ASTG + ((kt + 1) & 1) * 32768, tid);
            CP_COMMIT();
        }

        // ---- S = Q K^T (bf16 split, 3 terms) ----
        float S[2][8][4];
#pragma unroll
        for (int mi = 0; mi < 2; mi++)
#pragma unroll
            for (int ni = 0; ni < 8; ni++)
#pragma unroll
                for (int e = 0; e < 4; e++) S[mi][ni][e] = 0.f;

#pragma unroll
        for (int kc = 0; kc < 4; kc++) {
            uint32_t qfl[2][4];
#pragma unroll
            for (int mi = 0; mi < 2; mi++) {
                int row = warp * 32 + mi * 16 + (lane & 15);
                int ch  = kc * 2 + (lane >> 4);
                ldsm_x4(qfl[mi], sb + ASQL + row * 128 + ((ch ^ (row & 7)) << 4));
            }
#pragma unroll
            for (int ni = 0; ni < 8; ni++) {
                uint32_t kfh[2], kfl[2];
                int krow = ni * 8 + (lane & 7);
                int ch   = kc * 2 + ((lane >> 3) & 1);
                uint32_t koff = krow * 128 + ((ch ^ (krow & 7)) << 4);
                ldsm_x2(kfh, sbuf + AKH + koff);
                ldsm_x2(kfl, sbuf + AKL + koff);
#pragma unroll
                for (int mi = 0; mi < 2; mi++) {
                    mma_bf16(S[mi][ni], qfh[mi][kc], kfh);
                    mma_bf16(S[mi][ni], qfh[mi][kc], kfl);
                    mma_bf16(S[mi][ni], qfl[mi], kfh);
                }
            }
        }

        // ---- online softmax (base-2 domain) ----
        const int k0 = kt * 64;
        const bool need_mask = (kt >= 2 * qt);
#pragma unroll
        for (int mi = 0; mi < 2; mi++)
#pragma unroll
            for (int hh = 0; hh < 2; hh++) {
                int row = q0 + warp * 32 + mi * 16 + (lane >> 2) + hh * 8;
                float mx = -1e30f;
#pragma unroll
                for (int ni = 0; ni < 8; ni++)
#pragma unroll
                    for (int e = 0; e < 2; e++) {
                        float v = S[mi][ni][hh * 2 + e] * LOG2E_8;
                        if (need_mask) {
                            int col = k0 + ni * 8 + (lane & 3) * 2 + e;
                            if (col > row) v = -1e30f;
                        }
                        S[mi][ni][hh * 2 + e] = v;
                        mx = fmaxf(mx, v);
                    }
                mx = fmaxf(mx, __shfl_xor_sync(0xffffffffu, mx, 1));
                mx = fmaxf(mx, __shfl_xor_sync(0xffffffffu, mx, 2));
                float mnew = fmaxf(m_s[mi][hh], mx);
                float al = ex2f(m_s[mi][hh] - mnew);
                float sum = 0.f;
#pragma unroll
                for (int ni = 0; ni < 8; ni++)
#pragma unroll
                    for (int e = 0; e < 2; e++) {
                        float p = ex2f(S[mi][ni][hh * 2 + e] - mnew);
                        S[mi][ni][hh * 2 + e] = p;
                        sum += p;
                    }
                sum += __shfl_xor_sync(0xffffffffu, sum, 1);
                sum += __shfl_xor_sync(0xffffffffu, sum, 2);
                l_s[mi][hh] = l_s[mi][hh] * al + sum;
                m_s[mi][hh] = mnew;
#pragma unroll
                for (int nd = 0; nd < 8; nd++) {
                    O[mi][nd][hh * 2 + 0] *= al;
                    O[mi][nd][hh * 2 + 1] *= al;
                }
            }

        // ---- O += P V (P hi/lo split, 3 terms; V via ldmatrix.trans) ----
#pragma unroll
        for (int j = 0; j < 4; j++) {
            uint32_t pfh[2][4], pfl[2][4];
#pragma unroll
            for (int mi = 0; mi < 2; mi++) {
                float p00 = S[mi][2 * j][0],     p01 = S[mi][2 * j][1];
                float p02 = S[mi][2 * j][2],     p03 = S[mi][2 * j][3];
                float p10 = S[mi][2 * j + 1][0], p11 = S[mi][2 * j + 1][1];
                float p12 = S[mi][2 * j + 1][2], p13 = S[mi][2 * j + 1][3];
                float h00 = bf16_rt(p00), h01 = bf16_rt(p01);
                float h02 = bf16_rt(p02), h03 = bf16_rt(p03);
                float h10 = bf16_rt(p10), h11 = bf16_rt(p11);
                float h12 = bf16_rt(p12), h13 = bf16_rt(p13);
                pfh[mi][0] = pack_bf2(h00, h01);
                pfh[mi][1] = pack_bf2(h02, h03);
                pfh[mi][2] = pack_bf2(h10, h11);
                pfh[mi][3] = pack_bf2(h12, h13);
                pfl[mi][0] = pack_bf2(p00 - h00, p01 - h01);
                pfl[mi][1] = pack_bf2(p02 - h02, p03 - h03);
                pfl[mi][2] = pack_bf2(p10 - h10, p11 - h11);
                pfl[mi][3] = pack_bf2(p12 - h12, p13 - h13);
            }
#pragma unroll
            for (int nd = 0; nd < 8; nd++) {
                uint32_t vfh[2], vfl[2];
                int vrow = j * 16 + (lane & 15);
                uint32_t voff = vrow * 128 + ((nd ^ (vrow & 7)) << 4);
                ldsm_x2_t(vfh, sbuf + AVH + voff);
                ldsm_x2_t(vfl, sbuf + AVL + voff);
#pragma unroll
                for (int mi = 0; mi < 2; mi++) {
                    mma_bf16(O[mi][nd], pfh[mi], vfh);
                    mma_bf16(O[mi][nd], pfh[mi], vfl);
                    mma_bf16(O[mi][nd], pfl[mi], vfh);
                }
            }
        }

        if (kt + 1 < kts) { CP_WAIT(0); }
        __syncthreads();
    }

    // ---- epilogue: normalize, split to bf16 hi/lo ----
#pragma unroll
    for (int mi = 0; mi < 2; mi++)
#pragma unroll
        for (int hh = 0; hh < 2; hh++) {
            float inv = 1.f / l_s[mi][hh];
            int row = q0 + warp * 32 + mi * 16 + (lane >> 2) + hh * 8;
            size_t base = (size_t)(b * SEQ + row) * EMBED + h * HDIM;
#pragma unroll
            for (int nd = 0; nd < 8; nd++) {
                int d = nd * 8 + (lane & 3) * 2;
                float v0 = O[mi][nd][hh * 2 + 0] * inv;
                float v1 = O[mi][nd][hh * 2 + 1] * inv;
                float h0 = bf16_rt(v0);
                float h1 = bf16_rt(v1);
                *(uint32_t*)(xh + base + d) = pack_bf2(h0, h1);
                *(uint32_t*)(xl + base + d) = pack_bf2(v0 - h0, v1 - h1);
            }
        }
}

// ---------------------------------------------------------------------------
extern "C" void kernel_launch(void* const* d_in, const int* in_sizes, int n_in,
                              void* d_out, int out_size)
{
    const float* hs     = (const float*)d_in[0];
    const float* attn_w = (const float*)d_in[1];
    const float* attn_b = (const float*)d_in[2];
    const float* proj_w = (const float*)d_in[3];
    const float* proj_b = (const float*)d_in[4];
    float* out = (float*)d_out;

    __nv_bfloat16 *Ah, *Al, *Wqh, *Wql, *Wph, *Wpl, *QKVh, *QKVl, *Xh, *Xl;
    cudaGetSymbolAddress((void**)&Ah,   g_Ah);
    cudaGetSymbolAddress((void**)&Al,   g_Al);
    cudaGetSymbolAddress((void**)&Wqh,  g_Wqh);
    cudaGetSymbolAddress((void**)&Wql,  g_Wql);
    cudaGetSymbolAddress((void**)&Wph,  g_Wph);
    cudaGetSymbolAddress((void**)&Wpl,  g_Wpl);
    cudaGetSymbolAddress((void**)&QKVh, g_QKVh);
    cudaGetSymbolAddress((void**)&QKVl, g_QKVl);
    cudaGetSymbolAddress((void**)&Xh,   g_Xh);
    cudaGetSymbolAddress((void**)&Xl,   g_Xl);

    cudaFuncSetAttribute(gemm_hmma, cudaFuncAttributeMaxDynamicSharedMemorySize, 2 * GSTAGE);
    cudaFuncSetAttribute(gemm_hmma_split, cudaFuncAttributeMaxDynamicSharedMemorySize, 2 * GSTAGE);
    cudaFuncSetAttribute(attn_hmma, cudaFuncAttributeMaxDynamicSharedMemorySize, ASMEM);

    // 0) prepare split operands
    split_f32<<<2048, 256>>>(hs, Ah, Al, MTOT * EMBED / 4);
    transpose_split<<<dim3(3 * EMBED / 32, EMBED / 32), dim3(32, 8)>>>(attn_w, Wqh, Wql, EMBED, 3 * EMBED);
    transpose_split<<<dim3(EMBED / 32, EMBED / 32), dim3(32, 8)>>>(proj_w, Wph, Wpl, EMBED, EMBED);

    // 1) QKV projection -> bf16 hi/lo qkv
    gemm_hmma_split<<<dim3(3 * EMBED / 128, MTOT / 128), 256, 2 * GSTAGE>>>(
        Ah, Al, Wqh, Wql, attn_b, QKVh, QKVl, 3 * EMBED, EMBED);

    // 2) HMMA causal flash attention -> bf16 hi/lo X
    attn_hmma<<<dim3(SEQ / 128, BATCH * HEADS), 128, ASMEM>>>(QKVh, QKVl, Xh, Xl);

    // 3) output projection (fp32 out)
    gemm_hmma<<<dim3(EMBED / 128, MTOT / 128), 256, 2 * GSTAGE>>>(
        Xh, Xl, Wph, Wpl, proj_b, out, EMBED, EMBED);
}